// round 9
// baseline (speedup 1.0000x reference)
#include <cuda_runtime.h>

// SDPA: out = softmax(Q K^T / sqrt(D) + mask) V
// B=1, H=16, S=4096, D=64, all fp32. mask is [1,1,S,S] (head-independent).
//
// Round-0 baseline: numerically safe fp32 SIMT flash attention.
// One CTA = (head, 64-row Q tile). 256 threads as 16x16 (ty x tx).
// Smem: 3 x 16KB tiles, XOR-swizzled at float4 granularity for conflict-free
// LDS.128 on both the store and load patterns. K-tile region is reused to
// hold the P (probability) tile between the two GEMMs.

static constexpr int Hn = 16;
static constexpr int Sn = 4096;
static constexpr int Dn = 64;
static constexpr int BQ = 64;
static constexpr int BK = 64;

__global__ void __launch_bounds__(256)
sdpa_fp32_kernel(const float* __restrict__ Q,
                 const float* __restrict__ K,
                 const float* __restrict__ V,
                 const float* __restrict__ M,
                 float* __restrict__ O)
{
    // float4-granular tiles: [row][16 float4 units], unit index swizzled by row.
    __shared__ float4 q_sm[BQ * 16];
    __shared__ float4 kp_sm[BK * 16];   // K tile, then reused as P tile
    __shared__ float4 v_sm[BK * 16];

    const int tid = threadIdx.x;
    const int tx  = tid & 15;   // column-group lane
    const int ty  = tid >> 4;   // row-group lane
    const int q0  = blockIdx.x * BQ;
    const int h   = blockIdx.y;

    const float* __restrict__ Qh = Q + (size_t)h * Sn * Dn;
    const float* __restrict__ Kh = K + (size_t)h * Sn * Dn;
    const float* __restrict__ Vh = V + (size_t)h * Sn * Dn;

    // ---- Load Q tile (pre-scaled by 1/sqrt(D) = 0.125, exact in fp32) ----
    for (int i = tid; i < BQ * 16; i += 256) {
        const int row = i >> 4;
        const int d4  = i & 15;
        float4 qv = *reinterpret_cast<const float4*>(Qh + (q0 + row) * Dn + d4 * 4);
        qv.x *= 0.125f; qv.y *= 0.125f; qv.z *= 0.125f; qv.w *= 0.125f;
        q_sm[row * 16 + (d4 ^ (row & 15))] = qv;
    }

    // Per-thread state. Rows owned: r = ty + 16*jr (replicated across tx lanes
    // for m/l; O columns owned: dd = 4*tx + k).
    float o[4][4];
    float m_run[4], l_run[4];
    #pragma unroll
    for (int jr = 0; jr < 4; ++jr) {
        m_run[jr] = -1e30f;
        l_run[jr] = 0.0f;
        #pragma unroll
        for (int k = 0; k < 4; ++k) o[jr][k] = 0.0f;
    }

    for (int kt = 0; kt < Sn / BK; ++kt) {
        __syncthreads();   // previous iteration's PV reads of kp_sm/v_sm done

        // ---- Load K and V tiles (coalesced global, swizzled smem store) ----
        {
            const float* Kt = Kh + kt * BK * Dn;
            const float* Vt = Vh + kt * BK * Dn;
            for (int i = tid; i < BK * 16; i += 256) {
                const int row = i >> 4;
                const int d4  = i & 15;
                const int sw  = row * 16 + (d4 ^ (row & 15));
                kp_sm[sw] = *reinterpret_cast<const float4*>(Kt + row * Dn + d4 * 4);
                v_sm[sw]  = *reinterpret_cast<const float4*>(Vt + row * Dn + d4 * 4);
            }
        }
        __syncthreads();

        // ---- S = Qs K^T  (scores; thread tile rows r=ty+16jr, cols c=tx+16jc) ----
        float s[4][4];
        #pragma unroll
        for (int jr = 0; jr < 4; ++jr)
            #pragma unroll
            for (int jc = 0; jc < 4; ++jc) s[jr][jc] = 0.0f;

        #pragma unroll 4
        for (int d4 = 0; d4 < 16; ++d4) {
            float4 a[4], b[4];
            #pragma unroll
            for (int j = 0; j < 4; ++j) {
                const int r = ty + 16 * j;
                a[j] = q_sm[r * 16 + (d4 ^ (r & 15))];    // broadcast within half-warp
            }
            #pragma unroll
            for (int j = 0; j < 4; ++j) {
                const int c = tx + 16 * j;
                b[j] = kp_sm[c * 16 + (d4 ^ (c & 15))];   // conflict-free across tx
            }
            #pragma unroll
            for (int jr = 0; jr < 4; ++jr)
                #pragma unroll
                for (int jc = 0; jc < 4; ++jc) {
                    s[jr][jc] += a[jr].x * b[jc].x;
                    s[jr][jc] += a[jr].y * b[jc].y;
                    s[jr][jc] += a[jr].z * b[jc].z;
                    s[jr][jc] += a[jr].w * b[jc].w;
                }
        }

        // ---- additive mask (head-independent, coalesced across tx) ----
        #pragma unroll
        for (int jr = 0; jr < 4; ++jr) {
            const size_t mrow = (size_t)(q0 + ty + 16 * jr) * Sn + kt * BK;
            #pragma unroll
            for (int jc = 0; jc < 4; ++jc)
                s[jr][jc] += __ldg(M + mrow + tx + 16 * jc);
        }

        // ---- online softmax update (row reductions across the 16 tx lanes) ----
        float alpha[4];
        #pragma unroll
        for (int jr = 0; jr < 4; ++jr) {
            float rmax = s[jr][0];
            #pragma unroll
            for (int jc = 1; jc < 4; ++jc) rmax = fmaxf(rmax, s[jr][jc]);
            #pragma unroll
            for (int sh = 1; sh < 16; sh <<= 1)
                rmax = fmaxf(rmax, __shfl_xor_sync(0xffffffffu, rmax, sh));

            const float mnew = fmaxf(m_run[jr], rmax);
            alpha[jr] = __expf(m_run[jr] - mnew);
            m_run[jr] = mnew;

            float rsum = 0.0f;
            #pragma unroll
            for (int jc = 0; jc < 4; ++jc) {
                s[jr][jc] = __expf(s[jr][jc] - mnew);
                rsum += s[jr][jc];
            }
            #pragma unroll
            for (int sh = 1; sh < 16; sh <<= 1)
                rsum += __shfl_xor_sync(0xffffffffu, rsum, sh);

            l_run[jr] = l_run[jr] * alpha[jr] + rsum;
            #pragma unroll
            for (int k = 0; k < 4; ++k) o[jr][k] *= alpha[jr];
        }

        __syncthreads();   // done reading kp_sm as K

        // ---- write P tile into kp_sm (same float4-granular swizzle) ----
        {
            float* kp_w = reinterpret_cast<float*>(kp_sm);
            #pragma unroll
            for (int jr = 0; jr < 4; ++jr) {
                const int r = ty + 16 * jr;
                #pragma unroll
                for (int jc = 0; jc < 4; ++jc) {
                    const int c = tx + 16 * jc;
                    kp_w[r * 64 + ((((c >> 2) ^ (r & 15)) << 2) | (c & 3))] = s[jr][jc];
                }
            }
        }
        __syncthreads();

        // ---- O += P V  (thread tile rows r=ty+16jr, output dims dd=4tx..4tx+3) ----
        #pragma unroll 4
        for (int c4 = 0; c4 < 16; ++c4) {
            float4 a[4];
            #pragma unroll
            for (int jr = 0; jr < 4; ++jr) {
                const int r = ty + 16 * jr;
                a[jr] = kp_sm[r * 16 + (c4 ^ (r & 15))];   // P[r][4c4..4c4+3], broadcast
            }
            #pragma unroll
            for (int cc = 0; cc < 4; ++cc) {
                const int c = c4 * 4 + cc;
                const float4 b = v_sm[c * 16 + (tx ^ (c & 15))];   // V[c][4tx..4tx+3]
                #pragma unroll
                for (int jr = 0; jr < 4; ++jr) {
                    const float pa = (cc == 0) ? a[jr].x
                                   : (cc == 1) ? a[jr].y
                                   : (cc == 2) ? a[jr].z
                                               : a[jr].w;
                    o[jr][0] += pa * b.x;
                    o[jr][1] += pa * b.y;
                    o[jr][2] += pa * b.z;
                    o[jr][3] += pa * b.w;
                }
            }
        }
    }

    // ---- epilogue: normalize and store (coalesced float4) ----
    #pragma unroll
    for (int jr = 0; jr < 4; ++jr) {
        const float inv = 1.0f / l_run[jr];
        float4 ov;
        ov.x = o[jr][0] * inv;
        ov.y = o[jr][1] * inv;
        ov.z = o[jr][2] * inv;
        ov.w = o[jr][3] * inv;
        *reinterpret_cast<float4*>(
            O + (size_t)(h * Sn + q0 + ty + 16 * jr) * Dn + tx * 4) = ov;
    }
}

extern "C" void kernel_launch(void* const* d_in, const int* in_sizes, int n_in,
                              void* d_out, int out_size)
{
    (void)in_sizes; (void)n_in; (void)out_size;
    const float* Qp = (const float*)d_in[0];
    const float* Kp = (const float*)d_in[1];
    const float* Vp = (const float*)d_in[2];
    const float* Mp = (const float*)d_in[3];
    float* Op = (float*)d_out;

    dim3 grid(Sn / BQ, Hn);
    sdpa_fp32_kernel<<<grid, 256>>>(Qp, Kp, Vp, Mp, Op);
}

// round 10
// speedup vs baseline: 1.0014x; 1.0014x over previous
#include <cuda_runtime.h>

// SDPA: out = softmax(Q K^T / sqrt(D) + mask) V
// B=1, H=16, S=4096, D=64, all fp32. mask is [1,1,S,S] (head-independent).
//
// Round-0 baseline: numerically safe fp32 SIMT flash attention.
// One CTA = (head, 64-row Q tile). 256 threads as 16x16 (ty x tx).
// Smem: 3 x 16KB tiles, XOR-swizzled at float4 granularity for conflict-free
// LDS.128 on both the store and load patterns. K-tile region is reused to
// hold the P (probability) tile between the two GEMMs.

static constexpr int Hn = 16;
static constexpr int Sn = 4096;
static constexpr int Dn = 64;
static constexpr int BQ = 64;
static constexpr int BK = 64;

__global__ void __launch_bounds__(256)
sdpa_fp32_kernel(const float* __restrict__ Q,
                 const float* __restrict__ K,
                 const float* __restrict__ V,
                 const float* __restrict__ M,
                 float* __restrict__ O)
{
    // float4-granular tiles: [row][16 float4 units], unit index swizzled by row.
    __shared__ float4 q_sm[BQ * 16];
    __shared__ float4 kp_sm[BK * 16];   // K tile, then reused as P tile
    __shared__ float4 v_sm[BK * 16];

    const int tid = threadIdx.x;
    const int tx  = tid & 15;   // column-group lane
    const int ty  = tid >> 4;   // row-group lane
    const int q0  = blockIdx.x * BQ;
    const int h   = blockIdx.y;

    const float* __restrict__ Qh = Q + (size_t)h * Sn * Dn;
    const float* __restrict__ Kh = K + (size_t)h * Sn * Dn;
    const float* __restrict__ Vh = V + (size_t)h * Sn * Dn;

    // ---- Load Q tile (pre-scaled by 1/sqrt(D) = 0.125, exact in fp32) ----
    for (int i = tid; i < BQ * 16; i += 256) {
        const int row = i >> 4;
        const int d4  = i & 15;
        float4 qv = *reinterpret_cast<const float4*>(Qh + (q0 + row) * Dn + d4 * 4);
        qv.x *= 0.125f; qv.y *= 0.125f; qv.z *= 0.125f; qv.w *= 0.125f;
        q_sm[row * 16 + (d4 ^ (row & 15))] = qv;
    }

    // Per-thread state. Rows owned: r = ty + 16*jr (replicated across tx lanes
    // for m/l; O columns owned: dd = 4*tx + k).
    float o[4][4];
    float m_run[4], l_run[4];
    #pragma unroll
    for (int jr = 0; jr < 4; ++jr) {
        m_run[jr] = -1e30f;
        l_run[jr] = 0.0f;
        #pragma unroll
        for (int k = 0; k < 4; ++k) o[jr][k] = 0.0f;
    }

    for (int kt = 0; kt < Sn / BK; ++kt) {
        __syncthreads();   // previous iteration's PV reads of kp_sm/v_sm done

        // ---- Load K and V tiles (coalesced global, swizzled smem store) ----
        {
            const float* Kt = Kh + kt * BK * Dn;
            const float* Vt = Vh + kt * BK * Dn;
            for (int i = tid; i < BK * 16; i += 256) {
                const int row = i >> 4;
                const int d4  = i & 15;
                const int sw  = row * 16 + (d4 ^ (row & 15));
                kp_sm[sw] = *reinterpret_cast<const float4*>(Kt + row * Dn + d4 * 4);
                v_sm[sw]  = *reinterpret_cast<const float4*>(Vt + row * Dn + d4 * 4);
            }
        }
        __syncthreads();

        // ---- S = Qs K^T  (scores; thread tile rows r=ty+16jr, cols c=tx+16jc) ----
        float s[4][4];
        #pragma unroll
        for (int jr = 0; jr < 4; ++jr)
            #pragma unroll
            for (int jc = 0; jc < 4; ++jc) s[jr][jc] = 0.0f;

        #pragma unroll 4
        for (int d4 = 0; d4 < 16; ++d4) {
            float4 a[4], b[4];
            #pragma unroll
            for (int j = 0; j < 4; ++j) {
                const int r = ty + 16 * j;
                a[j] = q_sm[r * 16 + (d4 ^ (r & 15))];    // broadcast within half-warp
            }
            #pragma unroll
            for (int j = 0; j < 4; ++j) {
                const int c = tx + 16 * j;
                b[j] = kp_sm[c * 16 + (d4 ^ (c & 15))];   // conflict-free across tx
            }
            #pragma unroll
            for (int jr = 0; jr < 4; ++jr)
                #pragma unroll
                for (int jc = 0; jc < 4; ++jc) {
                    s[jr][jc] += a[jr].x * b[jc].x;
                    s[jr][jc] += a[jr].y * b[jc].y;
                    s[jr][jc] += a[jr].z * b[jc].z;
                    s[jr][jc] += a[jr].w * b[jc].w;
                }
        }

        // ---- additive mask (head-independent, coalesced across tx) ----
        #pragma unroll
        for (int jr = 0; jr < 4; ++jr) {
            const size_t mrow = (size_t)(q0 + ty + 16 * jr) * Sn + kt * BK;
            #pragma unroll
            for (int jc = 0; jc < 4; ++jc)
                s[jr][jc] += __ldg(M + mrow + tx + 16 * jc);
        }

        // ---- online softmax update (row reductions across the 16 tx lanes) ----
        float alpha[4];
        #pragma unroll
        for (int jr = 0; jr < 4; ++jr) {
            float rmax = s[jr][0];
            #pragma unroll
            for (int jc = 1; jc < 4; ++jc) rmax = fmaxf(rmax, s[jr][jc]);
            #pragma unroll
            for (int sh = 1; sh < 16; sh <<= 1)
                rmax = fmaxf(rmax, __shfl_xor_sync(0xffffffffu, rmax, sh));

            const float mnew = fmaxf(m_run[jr], rmax);
            alpha[jr] = __expf(m_run[jr] - mnew);
            m_run[jr] = mnew;

            float rsum = 0.0f;
            #pragma unroll
            for (int jc = 0; jc < 4; ++jc) {
                s[jr][jc] = __expf(s[jr][jc] - mnew);
                rsum += s[jr][jc];
            }
            #pragma unroll
            for (int sh = 1; sh < 16; sh <<= 1)
                rsum += __shfl_xor_sync(0xffffffffu, rsum, sh);

            l_run[jr] = l_run[jr] * alpha[jr] + rsum;
            #pragma unroll
            for (int k = 0; k < 4; ++k) o[jr][k] *= alpha[jr];
        }

        __syncthreads();   // done reading kp_sm as K

        // ---- write P tile into kp_sm (same float4-granular swizzle) ----
        {
            float* kp_w = reinterpret_cast<float*>(kp_sm);
            #pragma unroll
            for (int jr = 0; jr < 4; ++jr) {
                const int r = ty + 16 * jr;
                #pragma unroll
                for (int jc = 0; jc < 4; ++jc) {
                    const int c = tx + 16 * jc;
                    kp_w[r * 64 + ((((c >> 2) ^ (r & 15)) << 2) | (c & 3))] = s[jr][jc];
                }
            }
        }
        __syncthreads();

        // ---- O += P V  (thread tile rows r=ty+16jr, output dims dd=4tx..4tx+3) ----
        #pragma unroll 4
        for (int c4 = 0; c4 < 16; ++c4) {
            float4 a[4];
            #pragma unroll
            for (int jr = 0; jr < 4; ++jr) {
                const int r = ty + 16 * jr;
                a[jr] = kp_sm[r * 16 + (c4 ^ (r & 15))];   // P[r][4c4..4c4+3], broadcast
            }
            #pragma unroll
            for (int cc = 0; cc < 4; ++cc) {
                const int c = c4 * 4 + cc;
                const float4 b = v_sm[c * 16 + (tx ^ (c & 15))];   // V[c][4tx..4tx+3]
                #pragma unroll
                for (int jr = 0; jr < 4; ++jr) {
                    const float pa = (cc == 0) ? a[jr].x
                                   : (cc == 1) ? a[jr].y
                                   : (cc == 2) ? a[jr].z
                                               : a[jr].w;
                    o[jr][0] += pa * b.x;
                    o[jr][1] += pa * b.y;
                    o[jr][2] += pa * b.z;
                    o[jr][3] += pa * b.w;
                }
            }
        }
    }

    // ---- epilogue: normalize and store (coalesced float4) ----
    #pragma unroll
    for (int jr = 0; jr < 4; ++jr) {
        const float inv = 1.0f / l_run[jr];
        float4 ov;
        ov.x = o[jr][0] * inv;
        ov.y = o[jr][1] * inv;
        ov.z = o[jr][2] * inv;
        ov.w = o[jr][3] * inv;
        *reinterpret_cast<float4*>(
            O + (size_t)(h * Sn + q0 + ty + 16 * jr) * Dn + tx * 4) = ov;
    }
}

extern "C" void kernel_launch(void* const* d_in, const int* in_sizes, int n_in,
                              void* d_out, int out_size)
{
    (void)in_sizes; (void)n_in; (void)out_size;
    const float* Qp = (const float*)d_in[0];
    const float* Kp = (const float*)d_in[1];
    const float* Vp = (const float*)d_in[2];
    const float* Mp = (const float*)d_in[3];
    float* Op = (float*)d_out;

    dim3 grid(Sn / BQ, Hn);
    sdpa_fp32_kernel<<<grid, 256>>>(Qp, Kp, Vp, Mp, Op);
}

// round 13
// speedup vs baseline: 2.2278x; 2.2247x over previous
#include <cuda_runtime.h>
#include <cuda_fp16.h>
#include <stdint.h>

// ============================================================================
// FA2-style flash attention, fp16 inputs / fp32 accumulation, via
// ldmatrix + mma.sync.m16n8k16 (base sm_103 — tcgen05 is rejected by the
// harness's PTX target, so HMMA is the fastest available tensor path).
//
// B=1, H=16, S=4096, D=64, fp32 in/out. mask [1,1,S,S].
// CTA = (head, 64-row q tile), 128 threads = 4 warps; warp owns 16 q rows.
// ============================================================================

static constexpr int Hn = 16, Sn = 4096, Dn = 64;
static constexpr int BQ = 64, BK = 128;
static constexpr int NT = Sn / BK;           // 32 key tiles

// dynamic smem layout (fp16 tiles, 128B rows, 16B-chunk XOR swizzle)
static constexpr int Q_OFF = 0;                       // 64 rows  = 8192 B
static constexpr int K_OFF = 8192;                    // 2 x 128 rows = 32768 B
static constexpr int V_OFF = K_OFF + 2 * 16384;       // 2 x 128 rows = 32768 B
static constexpr int SMEM_TOTAL = V_OFF + 2 * 16384;  // 73728 B

__device__ __forceinline__ uint32_t smem_u32(const void* p) {
    uint32_t a;
    asm("{ .reg .u64 t; cvta.to.shared.u64 t, %1; cvt.u32.u64 %0, t; }" : "=r"(a) : "l"(p));
    return a;
}

__device__ __forceinline__ void ldsm4(uint32_t r[4], uint32_t addr) {
    asm volatile("ldmatrix.sync.aligned.m8n8.x4.shared.b16 {%0,%1,%2,%3}, [%4];"
                 : "=r"(r[0]), "=r"(r[1]), "=r"(r[2]), "=r"(r[3]) : "r"(addr));
}
__device__ __forceinline__ void ldsm4t(uint32_t r[4], uint32_t addr) {
    asm volatile("ldmatrix.sync.aligned.m8n8.x4.trans.shared.b16 {%0,%1,%2,%3}, [%4];"
                 : "=r"(r[0]), "=r"(r[1]), "=r"(r[2]), "=r"(r[3]) : "r"(addr));
}
__device__ __forceinline__ void mma16816(float c[4], const uint32_t a[4],
                                         uint32_t b0, uint32_t b1) {
    asm volatile(
        "mma.sync.aligned.m16n8k16.row.col.f32.f16.f16.f32 "
        "{%0,%1,%2,%3}, {%4,%5,%6,%7}, {%8,%9}, {%0,%1,%2,%3};"
        : "+f"(c[0]), "+f"(c[1]), "+f"(c[2]), "+f"(c[3])
        : "r"(a[0]), "r"(a[1]), "r"(a[2]), "r"(a[3]), "r"(b0), "r"(b1));
}

// fp32 global [rows x 64] -> fp16 swizzled smem tile (128B rows).
// chunk c (16B) of row r stored at chunk (c ^ (r & 7)).
__device__ __forceinline__ void load_tile_f16(const float* __restrict__ src,
                                              char* dst, int rows, int tid,
                                              float scale) {
    for (int i = tid; i < rows * 16; i += 128) {
        const int row = i >> 4, g = i & 15;
        float4 f = *reinterpret_cast<const float4*>(src + row * Dn + g * 4);
        __half2 h0 = __floats2half2_rn(f.x * scale, f.y * scale);
        __half2 h1 = __floats2half2_rn(f.z * scale, f.w * scale);
        const uint32_t byte = row * 128 + ((((g >> 1) ^ (row & 7)) << 4) | ((g & 1) << 3));
        *reinterpret_cast<__half2*>(dst + byte)     = h0;
        *reinterpret_cast<__half2*>(dst + byte + 4) = h1;
    }
}

__global__ void __launch_bounds__(128)
sdpa_hmma_kernel(const float* __restrict__ Q,
                 const float* __restrict__ K,
                 const float* __restrict__ V,
                 const float* __restrict__ M,
                 float* __restrict__ O)
{
    extern __shared__ char smem[];
    const uint32_t sb = smem_u32(smem);

    const int tid = threadIdx.x;
    const int wid = tid >> 5;
    const int lid = tid & 31;
    const int g   = lid >> 2;     // row-in-fragment group
    const int t   = lid & 3;      // col quad lane

    const int q0  = blockIdx.x * BQ;
    const int h   = blockIdx.y;
    const int wq0 = wid * 16;     // this warp's q-row base within the tile

    const float* __restrict__ Qh = Q + (size_t)h * Sn * Dn;
    const float* __restrict__ Kh = K + (size_t)h * Sn * Dn;
    const float* __restrict__ Vh = V + (size_t)h * Sn * Dn;

    // ---- prologue: stage Q (scaled 1/8), K/V tile 0 (buffer 0) ----
    load_tile_f16(Qh + (size_t)q0 * Dn, smem + Q_OFF, BQ, tid, 0.125f);
    load_tile_f16(Kh, smem + K_OFF, BK, tid, 1.0f);
    load_tile_f16(Vh, smem + V_OFF, BK, tid, 1.0f);
    __syncthreads();

    // ---- preload Q A-fragments: qa[ks][0..3], ks = d/16 step ----
    // x4: m0=rows g0-7 chunk 2ks | m1=rows 8-15 chunk 2ks | m2=rows 0-7 chunk
    // 2ks+1 | m3=rows 8-15 chunk 2ks+1  (matches a0..a3 of m16n8k16)
    uint32_t qa[4][4];
    {
        const int sel = lid >> 3;
        const int row = wq0 + (lid & 7) + ((sel & 1) << 3);
        #pragma unroll
        for (int ks = 0; ks < 4; ++ks) {
            const int chunk = 2 * ks + (sel >> 1);
            ldsm4(qa[ks], sb + Q_OFF + row * 128 + ((chunk ^ (row & 7)) << 4));
        }
    }

    // per-thread FA state: 2 rows (wq0+g, wq0+g+8)
    float m0 = -1e30f, m1 = -1e30f, l0 = 0.0f, l1 = 0.0f;
    float oa[8][4];
    #pragma unroll
    for (int j = 0; j < 8; ++j)
        #pragma unroll
        for (int k = 0; k < 4; ++k) oa[j][k] = 0.0f;

    const float* mrow0 = M + (size_t)(q0 + wq0 + g) * Sn;
    const float* mrow1 = M + (size_t)(q0 + wq0 + g + 8) * Sn;

    for (int kt = 0; kt < NT; ++kt) {
        const int buf  = kt & 1;
        const int nbuf = buf ^ 1;
        const uint32_t kbase = sb + K_OFF + buf * 16384;
        const uint32_t vbase = sb + V_OFF + buf * 16384;

        // ---- S = Q K^T : 16 n-tiles (8 keys each) x 4 k-steps ----
        float sc[16][4];
        #pragma unroll
        for (int j = 0; j < 16; ++j)
            #pragma unroll
            for (int k = 0; k < 4; ++k) sc[j][k] = 0.0f;

        {
            const int sel  = lid >> 3;
            const int rlo  = (lid & 7) + ((sel >> 1) << 3);  // key row offset within 16
            #pragma unroll
            for (int ks = 0; ks < 4; ++ks) {
                const int chunk = 2 * ks + (sel & 1);
                #pragma unroll
                for (int j = 0; j < 8; ++j) {          // key 16-groups
                    const int row = 16 * j + rlo;
                    uint32_t kb[4];
                    ldsm4(kb, kbase + row * 128 + ((chunk ^ (row & 7)) << 4));
                    mma16816(sc[2 * j],     qa[ks], kb[0], kb[1]);
                    mma16816(sc[2 * j + 1], qa[ks], kb[2], kb[3]);
                }
            }
        }

        // ---- prefetch next K/V tiles (overlaps with softmax + PV) ----
        if (kt + 1 < NT) {
            load_tile_f16(Kh + (size_t)(kt + 1) * BK * Dn,
                          smem + K_OFF + nbuf * 16384, BK, tid, 1.0f);
            load_tile_f16(Vh + (size_t)(kt + 1) * BK * Dn,
                          smem + V_OFF + nbuf * 16384, BK, tid, 1.0f);
        }

        // ---- add mask ----
        {
            const float* mp0 = mrow0 + kt * BK + 2 * t;
            const float* mp1 = mrow1 + kt * BK + 2 * t;
            #pragma unroll
            for (int j = 0; j < 16; ++j) {
                const float2 v0 = __ldg(reinterpret_cast<const float2*>(mp0 + 8 * j));
                const float2 v1 = __ldg(reinterpret_cast<const float2*>(mp1 + 8 * j));
                sc[j][0] += v0.x; sc[j][1] += v0.y;
                sc[j][2] += v1.x; sc[j][3] += v1.y;
            }
        }

        // ---- online softmax (rows are quad-local: reduce over t via shfl) ----
        float rmax0 = sc[0][0], rmax1 = sc[0][2];
        #pragma unroll
        for (int j = 0; j < 16; ++j) {
            rmax0 = fmaxf(rmax0, fmaxf(sc[j][0], sc[j][1]));
            rmax1 = fmaxf(rmax1, fmaxf(sc[j][2], sc[j][3]));
        }
        #pragma unroll
        for (int sh = 1; sh < 4; sh <<= 1) {
            rmax0 = fmaxf(rmax0, __shfl_xor_sync(0xffffffffu, rmax0, sh));
            rmax1 = fmaxf(rmax1, __shfl_xor_sync(0xffffffffu, rmax1, sh));
        }
        const float mn0 = fmaxf(m0, rmax0), mn1 = fmaxf(m1, rmax1);
        const float a0 = __expf(m0 - mn0), a1 = __expf(m1 - mn1);
        m0 = mn0; m1 = mn1;

        float ps0 = 0.0f, ps1 = 0.0f;
        #pragma unroll
        for (int j = 0; j < 16; ++j) {
            sc[j][0] = __expf(sc[j][0] - mn0); ps0 += sc[j][0];
            sc[j][1] = __expf(sc[j][1] - mn0); ps0 += sc[j][1];
            sc[j][2] = __expf(sc[j][2] - mn1); ps1 += sc[j][2];
            sc[j][3] = __expf(sc[j][3] - mn1); ps1 += sc[j][3];
        }
        #pragma unroll
        for (int sh = 1; sh < 4; sh <<= 1) {
            ps0 += __shfl_xor_sync(0xffffffffu, ps0, sh);
            ps1 += __shfl_xor_sync(0xffffffffu, ps1, sh);
        }
        l0 = l0 * a0 + ps0;
        l1 = l1 * a1 + ps1;
        #pragma unroll
        for (int j = 0; j < 8; ++j) {
            oa[j][0] *= a0; oa[j][1] *= a0;
            oa[j][2] *= a1; oa[j][3] *= a1;
        }

        // ---- O += P V : convert P just-in-time, 8 key-ksteps x 8 d-tiles ----
        {
            const int sel = lid >> 3;
            const int rlo = (lid & 7) + ((sel & 1) << 3);   // key row offset within 16
            #pragma unroll
            for (int j2 = 0; j2 < 8; ++j2) {                 // key 16-step
                uint32_t pa[4];
                {
                    __half2 h;
                    h = __floats2half2_rn(sc[2 * j2][0],     sc[2 * j2][1]);
                    pa[0] = *reinterpret_cast<uint32_t*>(&h);
                    h = __floats2half2_rn(sc[2 * j2][2],     sc[2 * j2][3]);
                    pa[1] = *reinterpret_cast<uint32_t*>(&h);
                    h = __floats2half2_rn(sc[2 * j2 + 1][0], sc[2 * j2 + 1][1]);
                    pa[2] = *reinterpret_cast<uint32_t*>(&h);
                    h = __floats2half2_rn(sc[2 * j2 + 1][2], sc[2 * j2 + 1][3]);
                    pa[3] = *reinterpret_cast<uint32_t*>(&h);
                }
                const int row = 16 * j2 + rlo;
                #pragma unroll
                for (int dp = 0; dp < 4; ++dp) {             // d 16-groups
                    const int chunk = 2 * dp + (sel >> 1);
                    uint32_t vb[4];
                    ldsm4t(vb, vbase + row * 128 + ((chunk ^ (row & 7)) << 4));
                    mma16816(oa[2 * dp],     pa, vb[0], vb[1]);
                    mma16816(oa[2 * dp + 1], pa, vb[2], vb[3]);
                }
            }
        }

        __syncthreads();   // prefetch(nbuf) visible; buf free for next prefetch
    }

    // ---- epilogue: normalize, store fp32 ----
    const float i0 = 1.0f / l0, i1 = 1.0f / l1;
    float* or0 = O + (size_t)(h * Sn + q0 + wq0 + g) * Dn + 2 * t;
    float* or1 = or0 + 8 * Dn;
    #pragma unroll
    for (int j = 0; j < 8; ++j) {
        float2 v0 = make_float2(oa[j][0] * i0, oa[j][1] * i0);
        float2 v1 = make_float2(oa[j][2] * i1, oa[j][3] * i1);
        *reinterpret_cast<float2*>(or0 + 8 * j) = v0;
        *reinterpret_cast<float2*>(or1 + 8 * j) = v1;
    }
}

extern "C" void kernel_launch(void* const* d_in, const int* in_sizes, int n_in,
                              void* d_out, int out_size)
{
    (void)in_sizes; (void)n_in; (void)out_size;
    const float* Qp = (const float*)d_in[0];
    const float* Kp = (const float*)d_in[1];
    const float* Vp = (const float*)d_in[2];
    const float* Mp = (const float*)d_in[3];
    float* Op = (float*)d_out;

    cudaFuncSetAttribute(sdpa_hmma_kernel,
                         cudaFuncAttributeMaxDynamicSharedMemorySize, SMEM_TOTAL);
    dim3 grid(Sn / BQ, Hn);
    sdpa_hmma_kernel<<<grid, 128, SMEM_TOTAL>>>(Qp, Kp, Vp, Mp, Op);
}

// round 14
// speedup vs baseline: 3.6523x; 1.6395x over previous
#include <cuda_runtime.h>
#include <cuda_fp16.h>
#include <stdint.h>

// ============================================================================
// FA2-style flash attention, fp16 inputs / fp32 accumulation, via
// ldmatrix + mma.sync.m16n8k16 (base sm_103 target: tcgen05 unavailable).
//
// B=1, H=16, S=4096, D=64, fp32 in/out. mask [1,1,S,S].
// CTA = (head, 64-row q tile), 128 threads = 4 warps; warp owns 16 q rows.
// BK=64 key tile, double-buffered. Softmax in log2 domain (ex2.approx).
// grid = (head, qtile) so concurrent heads share mask lines in L2.
// __launch_bounds__(128,4): 4 CTAs/SM (16 warps) for latency hiding.
// ============================================================================

static constexpr int Hn = 16, Sn = 4096, Dn = 64;
static constexpr int BQ = 64, BK = 64;
static constexpr int NT = Sn / BK;           // 64 key tiles

// dynamic smem layout (fp16 tiles, 128B rows, 16B-chunk XOR swizzle)
static constexpr int Q_OFF = 0;                       // 64 rows  = 8192 B
static constexpr int K_OFF = 8192;                    // 2 x 64 rows = 16384 B
static constexpr int V_OFF = K_OFF + 2 * 8192;        // 2 x 64 rows = 16384 B
static constexpr int SMEM_TOTAL = V_OFF + 2 * 8192;   // 40960 B

__device__ __forceinline__ uint32_t smem_u32(const void* p) {
    uint32_t a;
    asm("{ .reg .u64 t; cvta.to.shared.u64 t, %1; cvt.u32.u64 %0, t; }" : "=r"(a) : "l"(p));
    return a;
}
__device__ __forceinline__ float ex2f(float x) {
    float r;
    asm("ex2.approx.ftz.f32 %0, %1;" : "=f"(r) : "f"(x));
    return r;
}
__device__ __forceinline__ void ldsm4(uint32_t r[4], uint32_t addr) {
    asm volatile("ldmatrix.sync.aligned.m8n8.x4.shared.b16 {%0,%1,%2,%3}, [%4];"
                 : "=r"(r[0]), "=r"(r[1]), "=r"(r[2]), "=r"(r[3]) : "r"(addr));
}
__device__ __forceinline__ void ldsm4t(uint32_t r[4], uint32_t addr) {
    asm volatile("ldmatrix.sync.aligned.m8n8.x4.trans.shared.b16 {%0,%1,%2,%3}, [%4];"
                 : "=r"(r[0]), "=r"(r[1]), "=r"(r[2]), "=r"(r[3]) : "r"(addr));
}
__device__ __forceinline__ void mma16816(float c[4], const uint32_t a[4],
                                         uint32_t b0, uint32_t b1) {
    asm volatile(
        "mma.sync.aligned.m16n8k16.row.col.f32.f16.f16.f32 "
        "{%0,%1,%2,%3}, {%4,%5,%6,%7}, {%8,%9}, {%0,%1,%2,%3};"
        : "+f"(c[0]), "+f"(c[1]), "+f"(c[2]), "+f"(c[3])
        : "r"(a[0]), "r"(a[1]), "r"(a[2]), "r"(a[3]), "r"(b0), "r"(b1));
}

// fp32 global [64 x 64] -> fp16 swizzled smem tile (128B rows).
// chunk c (16B) of row r stored at chunk (c ^ (r & 7)).
__device__ __forceinline__ void load_tile_f16(const float* __restrict__ src,
                                              char* dst, int tid, float scale) {
    #pragma unroll
    for (int it = 0; it < 8; ++it) {
        const int i = tid + it * 128;
        const int row = i >> 4, g = i & 15;
        float4 f = *reinterpret_cast<const float4*>(src + row * Dn + g * 4);
        __half2 h0 = __floats2half2_rn(f.x * scale, f.y * scale);
        __half2 h1 = __floats2half2_rn(f.z * scale, f.w * scale);
        const uint32_t byte = row * 128 + ((((g >> 1) ^ (row & 7)) << 4) | ((g & 1) << 3));
        *reinterpret_cast<__half2*>(dst + byte)     = h0;
        *reinterpret_cast<__half2*>(dst + byte + 4) = h1;
    }
}

__global__ void __launch_bounds__(128, 4)
sdpa_hmma_kernel(const float* __restrict__ Q,
                 const float* __restrict__ K,
                 const float* __restrict__ V,
                 const float* __restrict__ M,
                 float* __restrict__ O)
{
    extern __shared__ char smem[];
    const uint32_t sb = smem_u32(smem);

    const int tid = threadIdx.x;
    const int wid = tid >> 5;
    const int lid = tid & 31;
    const int g   = lid >> 2;     // row-in-fragment group
    const int t   = lid & 3;      // col quad lane

    const int h   = blockIdx.x;             // head on x: concurrent heads share mask in L2
    const int q0  = blockIdx.y * BQ;
    const int wq0 = wid * 16;     // this warp's q-row base within the tile

    const float* __restrict__ Qh = Q + (size_t)h * Sn * Dn;
    const float* __restrict__ Kh = K + (size_t)h * Sn * Dn;
    const float* __restrict__ Vh = V + (size_t)h * Sn * Dn;

    constexpr float LOG2E = 1.4426950408889634f;

    // ---- prologue: stage Q (scaled 1/8 * log2e), K/V tile 0 (buffer 0) ----
    load_tile_f16(Qh + (size_t)q0 * Dn, smem + Q_OFF, tid, 0.125f * LOG2E);
    load_tile_f16(Kh, smem + K_OFF, tid, 1.0f);
    load_tile_f16(Vh, smem + V_OFF, tid, 1.0f);
    __syncthreads();

    // ---- preload Q A-fragments: qa[ks][0..3], ks = d/16 step ----
    uint32_t qa[4][4];
    {
        const int sel = lid >> 3;
        const int row = wq0 + (lid & 7) + ((sel & 1) << 3);
        #pragma unroll
        for (int ks = 0; ks < 4; ++ks) {
            const int chunk = 2 * ks + (sel >> 1);
            ldsm4(qa[ks], sb + Q_OFF + row * 128 + ((chunk ^ (row & 7)) << 4));
        }
    }

    // per-thread FA state: 2 rows (wq0+g, wq0+g+8); m/l in log2 domain for m
    float m0 = -1e30f, m1 = -1e30f, l0 = 0.0f, l1 = 0.0f;
    float oa[8][4];
    #pragma unroll
    for (int j = 0; j < 8; ++j)
        #pragma unroll
        for (int k = 0; k < 4; ++k) oa[j][k] = 0.0f;

    const float* mrow0 = M + (size_t)(q0 + wq0 + g) * Sn;
    const float* mrow1 = M + (size_t)(q0 + wq0 + g + 8) * Sn;

    for (int kt = 0; kt < NT; ++kt) {
        const int buf  = kt & 1;
        const int nbuf = buf ^ 1;
        const uint32_t kbase = sb + K_OFF + buf * 8192;
        const uint32_t vbase = sb + V_OFF + buf * 8192;

        // ---- S(log2) = Q K^T : 8 n-tiles (8 keys each) x 4 k-steps ----
        float sc[8][4];
        #pragma unroll
        for (int j = 0; j < 8; ++j)
            #pragma unroll
            for (int k = 0; k < 4; ++k) sc[j][k] = 0.0f;

        {
            const int sel = lid >> 3;
            const int rlo = (lid & 7) + ((sel >> 1) << 3);   // key row offset within 16
            #pragma unroll
            for (int ks = 0; ks < 4; ++ks) {
                const int chunk = 2 * ks + (sel & 1);
                #pragma unroll
                for (int j = 0; j < 4; ++j) {                // key 16-groups
                    const int row = 16 * j + rlo;
                    uint32_t kb[4];
                    ldsm4(kb, kbase + row * 128 + ((chunk ^ (row & 7)) << 4));
                    mma16816(sc[2 * j],     qa[ks], kb[0], kb[1]);
                    mma16816(sc[2 * j + 1], qa[ks], kb[2], kb[3]);
                }
            }
        }

        // ---- prefetch next K/V tiles (overlaps with softmax + PV) ----
        if (kt + 1 < NT) {
            load_tile_f16(Kh + (size_t)(kt + 1) * BK * Dn,
                          smem + K_OFF + nbuf * 8192, tid, 1.0f);
            load_tile_f16(Vh + (size_t)(kt + 1) * BK * Dn,
                          smem + V_OFF + nbuf * 8192, tid, 1.0f);
        }

        // ---- add mask (scaled to log2 domain via FFMA) ----
        {
            const float* mp0 = mrow0 + kt * BK + 2 * t;
            const float* mp1 = mrow1 + kt * BK + 2 * t;
            #pragma unroll
            for (int j = 0; j < 8; ++j) {
                const float2 v0 = __ldg(reinterpret_cast<const float2*>(mp0 + 8 * j));
                const float2 v1 = __ldg(reinterpret_cast<const float2*>(mp1 + 8 * j));
                sc[j][0] = fmaf(v0.x, LOG2E, sc[j][0]);
                sc[j][1] = fmaf(v0.y, LOG2E, sc[j][1]);
                sc[j][2] = fmaf(v1.x, LOG2E, sc[j][2]);
                sc[j][3] = fmaf(v1.y, LOG2E, sc[j][3]);
            }
        }

        // ---- online softmax in log2 domain (quad-local rows, shfl over t) ----
        float rmax0 = sc[0][0], rmax1 = sc[0][2];
        #pragma unroll
        for (int j = 0; j < 8; ++j) {
            rmax0 = fmaxf(rmax0, fmaxf(sc[j][0], sc[j][1]));
            rmax1 = fmaxf(rmax1, fmaxf(sc[j][2], sc[j][3]));
        }
        #pragma unroll
        for (int sh = 1; sh < 4; sh <<= 1) {
            rmax0 = fmaxf(rmax0, __shfl_xor_sync(0xffffffffu, rmax0, sh));
            rmax1 = fmaxf(rmax1, __shfl_xor_sync(0xffffffffu, rmax1, sh));
        }
        const float mn0 = fmaxf(m0, rmax0), mn1 = fmaxf(m1, rmax1);
        const float a0 = ex2f(m0 - mn0), a1 = ex2f(m1 - mn1);
        m0 = mn0; m1 = mn1;

        float ps0 = 0.0f, ps1 = 0.0f;
        #pragma unroll
        for (int j = 0; j < 8; ++j) {
            sc[j][0] = ex2f(sc[j][0] - mn0); ps0 += sc[j][0];
            sc[j][1] = ex2f(sc[j][1] - mn0); ps0 += sc[j][1];
            sc[j][2] = ex2f(sc[j][2] - mn1); ps1 += sc[j][2];
            sc[j][3] = ex2f(sc[j][3] - mn1); ps1 += sc[j][3];
        }
        #pragma unroll
        for (int sh = 1; sh < 4; sh <<= 1) {
            ps0 += __shfl_xor_sync(0xffffffffu, ps0, sh);
            ps1 += __shfl_xor_sync(0xffffffffu, ps1, sh);
        }
        l0 = l0 * a0 + ps0;
        l1 = l1 * a1 + ps1;
        #pragma unroll
        for (int j = 0; j < 8; ++j) {
            oa[j][0] *= a0; oa[j][1] *= a0;
            oa[j][2] *= a1; oa[j][3] *= a1;
        }

        // ---- O += P V : convert P just-in-time, 4 key-ksteps x 4 d-tiles ----
        {
            const int sel = lid >> 3;
            const int rlo = (lid & 7) + ((sel & 1) << 3);   // key row offset within 16
            #pragma unroll
            for (int j2 = 0; j2 < 4; ++j2) {                 // key 16-step
                uint32_t pa[4];
                {
                    __half2 hh;
                    hh = __floats2half2_rn(sc[2 * j2][0],     sc[2 * j2][1]);
                    pa[0] = *reinterpret_cast<uint32_t*>(&hh);
                    hh = __floats2half2_rn(sc[2 * j2][2],     sc[2 * j2][3]);
                    pa[1] = *reinterpret_cast<uint32_t*>(&hh);
                    hh = __floats2half2_rn(sc[2 * j2 + 1][0], sc[2 * j2 + 1][1]);
                    pa[2] = *reinterpret_cast<uint32_t*>(&hh);
                    hh = __floats2half2_rn(sc[2 * j2 + 1][2], sc[2 * j2 + 1][3]);
                    pa[3] = *reinterpret_cast<uint32_t*>(&hh);
                }
                const int row = 16 * j2 + rlo;
                #pragma unroll
                for (int dp = 0; dp < 4; ++dp) {             // d 16-groups
                    const int chunk = 2 * dp + (sel >> 1);
                    uint32_t vb[4];
                    ldsm4t(vb, vbase + row * 128 + ((chunk ^ (row & 7)) << 4));
                    mma16816(oa[2 * dp],     pa, vb[0], vb[1]);
                    mma16816(oa[2 * dp + 1], pa, vb[2], vb[3]);
                }
            }
        }

        __syncthreads();   // prefetch(nbuf) visible; buf free for next prefetch
    }

    // ---- epilogue: normalize, store fp32 ----
    const float i0 = 1.0f / l0, i1 = 1.0f / l1;
    float* or0 = O + (size_t)(h * Sn + q0 + wq0 + g) * Dn + 2 * t;
    float* or1 = or0 + 8 * Dn;
    #pragma unroll
    for (int j = 0; j < 8; ++j) {
        float2 v0 = make_float2(oa[j][0] * i0, oa[j][1] * i0);
        float2 v1 = make_float2(oa[j][2] * i1, oa[j][3] * i1);
        *reinterpret_cast<float2*>(or0 + 8 * j) = v0;
        *reinterpret_cast<float2*>(or1 + 8 * j) = v1;
    }
}

extern "C" void kernel_launch(void* const* d_in, const int* in_sizes, int n_in,
                              void* d_out, int out_size)
{
    (void)in_sizes; (void)n_in; (void)out_size;
    const float* Qp = (const float*)d_in[0];
    const float* Kp = (const float*)d_in[1];
    const float* Vp = (const float*)d_in[2];
    const float* Mp = (const float*)d_in[3];
    float* Op = (float*)d_out;

    cudaFuncSetAttribute(sdpa_hmma_kernel,
                         cudaFuncAttributeMaxDynamicSharedMemorySize, SMEM_TOTAL);
    dim3 grid(Hn, Sn / BQ);
    sdpa_hmma_kernel<<<grid, 128, SMEM_TOTAL>>>(Qp, Kp, Vp, Mp, Op);
}

// round 15
// speedup vs baseline: 6.9256x; 1.8962x over previous
#include <cuda_runtime.h>
#include <cuda_fp16.h>
#include <stdint.h>

// ============================================================================
// FA2-style flash attention, fp16 inputs / fp32 accumulation, via
// ldmatrix + mma.sync.m16n8k16 (base sm_103 target: tcgen05 unavailable).
//
// Two kernels:
//  1) convert_kernel: Q/K/V fp32 -> fp16, pre-swizzled into 8KB smem-tile
//     images in __device__ scratch (Q pre-scaled by 0.125*log2(e)).
//  2) main kernel: cp.async tile pipeline (no reg staging), hoisted mask
//     loads, log2-domain softmax, deferred l-reduction.
// ============================================================================

static constexpr int Hn = 16, Sn = 4096, Dn = 64;
static constexpr int BQ = 64, BK = 64;
static constexpr int NT = Sn / BK;           // 64 key tiles
static constexpr int TILE_ELEMS = 64 * 64;   // 4096 fp16 = 8KB

// fp16 pre-swizzled tile scratch (16 heads x 64 tiles x 4096 halfs = 8MB each)
__device__ __half QT_g[Hn * NT * TILE_ELEMS];
__device__ __half KT_g[Hn * NT * TILE_ELEMS];
__device__ __half VT_g[Hn * NT * TILE_ELEMS];

// dynamic smem layout in main kernel
static constexpr int Q_OFF = 0;                       // 8192 B
static constexpr int K_OFF = 8192;                    // 2 x 8192 B
static constexpr int V_OFF = K_OFF + 2 * 8192;        // 2 x 8192 B
static constexpr int SMEM_TOTAL = V_OFF + 2 * 8192;   // 40960 B

__device__ __forceinline__ uint32_t smem_u32(const void* p) {
    uint32_t a;
    asm("{ .reg .u64 t; cvta.to.shared.u64 t, %1; cvt.u32.u64 %0, t; }" : "=r"(a) : "l"(p));
    return a;
}
__device__ __forceinline__ float ex2f(float x) {
    float r;
    asm("ex2.approx.ftz.f32 %0, %1;" : "=f"(r) : "f"(x));
    return r;
}
__device__ __forceinline__ void ldsm4(uint32_t r[4], uint32_t addr) {
    asm volatile("ldmatrix.sync.aligned.m8n8.x4.shared.b16 {%0,%1,%2,%3}, [%4];"
                 : "=r"(r[0]), "=r"(r[1]), "=r"(r[2]), "=r"(r[3]) : "r"(addr));
}
__device__ __forceinline__ void ldsm4t(uint32_t r[4], uint32_t addr) {
    asm volatile("ldmatrix.sync.aligned.m8n8.x4.trans.shared.b16 {%0,%1,%2,%3}, [%4];"
                 : "=r"(r[0]), "=r"(r[1]), "=r"(r[2]), "=r"(r[3]) : "r"(addr));
}
__device__ __forceinline__ void mma16816(float c[4], const uint32_t a[4],
                                         uint32_t b0, uint32_t b1) {
    asm volatile(
        "mma.sync.aligned.m16n8k16.row.col.f32.f16.f16.f32 "
        "{%0,%1,%2,%3}, {%4,%5,%6,%7}, {%8,%9}, {%0,%1,%2,%3};"
        : "+f"(c[0]), "+f"(c[1]), "+f"(c[2]), "+f"(c[3])
        : "r"(a[0]), "r"(a[1]), "r"(a[2]), "r"(a[3]), "r"(b0), "r"(b1));
}
__device__ __forceinline__ void cpa16(uint32_t sdst, const void* gsrc) {
    asm volatile("cp.async.cg.shared.global [%0], [%1], 16;" :: "r"(sdst), "l"(gsrc));
}
#define CP_COMMIT() asm volatile("cp.async.commit_group;" ::: "memory")
#define CP_WAIT0()  asm volatile("cp.async.wait_group 0;" ::: "memory")

// one 8KB tile: 128 threads x 4 x 16B
__device__ __forceinline__ void cpa_tile(uint32_t sdst, const char* gsrc, int tid) {
    #pragma unroll
    for (int it = 0; it < 4; ++it)
        cpa16(sdst + tid * 16 + it * 2048, gsrc + tid * 16 + it * 2048);
}

// ---------------------------------------------------------------------------
// convert kernel: fp32 [64 x 64] block -> fp16 swizzled 8KB tile image.
// grid = (NT, Hn, 3), 128 threads. which: 0=Q (scaled), 1=K, 2=V.
// ---------------------------------------------------------------------------
__global__ void __launch_bounds__(128)
convert_kernel(const float* __restrict__ Q,
               const float* __restrict__ K,
               const float* __restrict__ V)
{
    constexpr float LOG2E = 1.4426950408889634f;
    const int tile = blockIdx.x, h = blockIdx.y, which = blockIdx.z;
    const int tid = threadIdx.x;

    const float* src = (which == 0 ? Q : which == 1 ? K : V)
                     + ((size_t)h * Sn + (size_t)tile * 64) * Dn;
    __half* dsth = (which == 0 ? QT_g : which == 1 ? KT_g : VT_g)
                 + (size_t)(h * NT + tile) * TILE_ELEMS;
    char* dst = reinterpret_cast<char*>(dsth);
    const float scale = (which == 0) ? 0.125f * LOG2E : 1.0f;

    #pragma unroll
    for (int it = 0; it < 8; ++it) {
        const int i = tid + it * 128;
        const int row = i >> 4, g = i & 15;
        float4 f = *reinterpret_cast<const float4*>(src + row * Dn + g * 4);
        __half2 h0 = __floats2half2_rn(f.x * scale, f.y * scale);
        __half2 h1 = __floats2half2_rn(f.z * scale, f.w * scale);
        const uint32_t byte = row * 128 + ((((g >> 1) ^ (row & 7)) << 4) | ((g & 1) << 3));
        *reinterpret_cast<__half2*>(dst + byte)     = h0;
        *reinterpret_cast<__half2*>(dst + byte + 4) = h1;
    }
}

// ---------------------------------------------------------------------------
// main attention kernel
// ---------------------------------------------------------------------------
__global__ void __launch_bounds__(128, 4)
sdpa_hmma_kernel(const float* __restrict__ M, float* __restrict__ O)
{
    extern __shared__ char smem[];
    const uint32_t sb = smem_u32(smem);

    const int tid = threadIdx.x;
    const int wid = tid >> 5;
    const int lid = tid & 31;
    const int g   = lid >> 2;     // row-in-fragment group
    const int t   = lid & 3;      // col quad lane

    const int h   = blockIdx.x;   // heads adjacent: share mask lines in L2
    const int qt  = blockIdx.y;
    const int q0  = qt * BQ;
    const int wq0 = wid * 16;

    constexpr float LOG2E = 1.4426950408889634f;

    const char* Qg = reinterpret_cast<const char*>(QT_g + (size_t)(h * NT + qt) * TILE_ELEMS);
    const char* Kg = reinterpret_cast<const char*>(KT_g + (size_t)h * NT * TILE_ELEMS);
    const char* Vg = reinterpret_cast<const char*>(VT_g + (size_t)h * NT * TILE_ELEMS);

    // ---- prologue: async-stage Q, K0, V0 ----
    cpa_tile(sb + Q_OFF, Qg, tid);
    cpa_tile(sb + K_OFF, Kg, tid);
    cpa_tile(sb + V_OFF, Vg, tid);
    CP_COMMIT();
    CP_WAIT0();
    __syncthreads();

    // ---- preload Q A-fragments: qa[ks][0..3] ----
    uint32_t qa[4][4];
    {
        const int sel = lid >> 3;
        const int row = wq0 + (lid & 7) + ((sel & 1) << 3);
        #pragma unroll
        for (int ks = 0; ks < 4; ++ks) {
            const int chunk = 2 * ks + (sel >> 1);
            ldsm4(qa[ks], sb + Q_OFF + row * 128 + ((chunk ^ (row & 7)) << 4));
        }
    }

    // per-thread FA state: rows (wq0+g, wq0+g+8); l kept lane-partial
    float m0 = -1e30f, m1 = -1e30f, l0 = 0.0f, l1 = 0.0f;
    float oa[8][4];
    #pragma unroll
    for (int j = 0; j < 8; ++j)
        #pragma unroll
        for (int k = 0; k < 4; ++k) oa[j][k] = 0.0f;

    const float* mrow0 = M + (size_t)(q0 + wq0 + g) * Sn + 2 * t;
    const float* mrow1 = M + (size_t)(q0 + wq0 + g + 8) * Sn + 2 * t;

    for (int kt = 0; kt < NT; ++kt) {
        const int buf  = kt & 1;
        const int nbuf = buf ^ 1;
        const uint32_t kbase = sb + K_OFF + buf * 8192;
        const uint32_t vbase = sb + V_OFF + buf * 8192;

        // ---- issue next-tile prefetch first (fully async) ----
        if (kt + 1 < NT) {
            cpa_tile(sb + K_OFF + nbuf * 8192, Kg + (size_t)(kt + 1) * 8192, tid);
            cpa_tile(sb + V_OFF + nbuf * 8192, Vg + (size_t)(kt + 1) * 8192, tid);
            CP_COMMIT();
        }

        // ---- hoisted mask loads (latency covered by the S-GEMM below) ----
        float2 mv0[8], mv1[8];
        {
            const float* mp0 = mrow0 + kt * BK;
            const float* mp1 = mrow1 + kt * BK;
            #pragma unroll
            for (int j = 0; j < 8; ++j) {
                mv0[j] = __ldg(reinterpret_cast<const float2*>(mp0 + 8 * j));
                mv1[j] = __ldg(reinterpret_cast<const float2*>(mp1 + 8 * j));
            }
        }

        // ---- S(log2) = Q K^T : 4 key-16-groups x 4 k-steps ----
        float sc[8][4];
        #pragma unroll
        for (int j = 0; j < 8; ++j)
            #pragma unroll
            for (int k = 0; k < 4; ++k) sc[j][k] = 0.0f;

        {
            const int sel = lid >> 3;
            const int rlo = (lid & 7) + ((sel >> 1) << 3);
            #pragma unroll
            for (int ks = 0; ks < 4; ++ks) {
                const int chunk = 2 * ks + (sel & 1);
                #pragma unroll
                for (int j = 0; j < 4; ++j) {
                    const int row = 16 * j + rlo;
                    uint32_t kb[4];
                    ldsm4(kb, kbase + row * 128 + ((chunk ^ (row & 7)) << 4));
                    mma16816(sc[2 * j],     qa[ks], kb[0], kb[1]);
                    mma16816(sc[2 * j + 1], qa[ks], kb[2], kb[3]);
                }
            }
        }

        // ---- apply mask (log2 domain) ----
        #pragma unroll
        for (int j = 0; j < 8; ++j) {
            sc[j][0] = fmaf(mv0[j].x, LOG2E, sc[j][0]);
            sc[j][1] = fmaf(mv0[j].y, LOG2E, sc[j][1]);
            sc[j][2] = fmaf(mv1[j].x, LOG2E, sc[j][2]);
            sc[j][3] = fmaf(mv1[j].y, LOG2E, sc[j][3]);
        }

        // ---- online softmax (max over quad; sum stays lane-partial) ----
        float rmax0 = sc[0][0], rmax1 = sc[0][2];
        #pragma unroll
        for (int j = 0; j < 8; ++j) {
            rmax0 = fmaxf(rmax0, fmaxf(sc[j][0], sc[j][1]));
            rmax1 = fmaxf(rmax1, fmaxf(sc[j][2], sc[j][3]));
        }
        #pragma unroll
        for (int sh = 1; sh < 4; sh <<= 1) {
            rmax0 = fmaxf(rmax0, __shfl_xor_sync(0xffffffffu, rmax0, sh));
            rmax1 = fmaxf(rmax1, __shfl_xor_sync(0xffffffffu, rmax1, sh));
        }
        const float mn0 = fmaxf(m0, rmax0), mn1 = fmaxf(m1, rmax1);
        const float a0 = ex2f(m0 - mn0), a1 = ex2f(m1 - mn1);
        m0 = mn0; m1 = mn1;

        float ps0 = 0.0f, ps1 = 0.0f;
        #pragma unroll
        for (int j = 0; j < 8; ++j) {
            sc[j][0] = ex2f(sc[j][0] - mn0); ps0 += sc[j][0];
            sc[j][1] = ex2f(sc[j][1] - mn0); ps0 += sc[j][1];
            sc[j][2] = ex2f(sc[j][2] - mn1); ps1 += sc[j][2];
            sc[j][3] = ex2f(sc[j][3] - mn1); ps1 += sc[j][3];
        }
        l0 = l0 * a0 + ps0;         // lane-partial sums; reduced in epilogue
        l1 = l1 * a1 + ps1;
        #pragma unroll
        for (int j = 0; j < 8; ++j) {
            oa[j][0] *= a0; oa[j][1] *= a0;
            oa[j][2] *= a1; oa[j][3] *= a1;
        }

        // ---- O += P V : convert P just-in-time ----
        {
            const int sel = lid >> 3;
            const int rlo = (lid & 7) + ((sel & 1) << 3);
            #pragma unroll
            for (int j2 = 0; j2 < 4; ++j2) {
                uint32_t pa[4];
                {
                    __half2 hh;
                    hh = __floats2half2_rn(sc[2 * j2][0],     sc[2 * j2][1]);
                    pa[0] = *reinterpret_cast<uint32_t*>(&hh);
                    hh = __floats2half2_rn(sc[2 * j2][2],     sc[2 * j2][3]);
                    pa[1] = *reinterpret_cast<uint32_t*>(&hh);
                    hh = __floats2half2_rn(sc[2 * j2 + 1][0], sc[2 * j2 + 1][1]);
                    pa[2] = *reinterpret_cast<uint32_t*>(&hh);
                    hh = __floats2half2_rn(sc[2 * j2 + 1][2], sc[2 * j2 + 1][3]);
                    pa[3] = *reinterpret_cast<uint32_t*>(&hh);
                }
                const int row = 16 * j2 + rlo;
                #pragma unroll
                for (int dp = 0; dp < 4; ++dp) {
                    const int chunk = 2 * dp + (sel >> 1);
                    uint32_t vb[4];
                    ldsm4t(vb, vbase + row * 128 + ((chunk ^ (row & 7)) << 4));
                    mma16816(oa[2 * dp],     pa, vb[0], vb[1]);
                    mma16816(oa[2 * dp + 1], pa, vb[2], vb[3]);
                }
            }
        }

        CP_WAIT0();        // next tile landed
        __syncthreads();   // all warps done with buf; nbuf visible
    }

    // ---- epilogue: reduce l over quad, normalize, store fp32 ----
    #pragma unroll
    for (int sh = 1; sh < 4; sh <<= 1) {
        l0 += __shfl_xor_sync(0xffffffffu, l0, sh);
        l1 += __shfl_xor_sync(0xffffffffu, l1, sh);
    }
    const float i0 = 1.0f / l0, i1 = 1.0f / l1;
    float* or0 = O + (size_t)(h * Sn + q0 + wq0 + g) * Dn + 2 * t;
    float* or1 = or0 + 8 * Dn;
    #pragma unroll
    for (int j = 0; j < 8; ++j) {
        float2 v0 = make_float2(oa[j][0] * i0, oa[j][1] * i0);
        float2 v1 = make_float2(oa[j][2] * i1, oa[j][3] * i1);
        *reinterpret_cast<float2*>(or0 + 8 * j) = v0;
        *reinterpret_cast<float2*>(or1 + 8 * j) = v1;
    }
}

extern "C" void kernel_launch(void* const* d_in, const int* in_sizes, int n_in,
                              void* d_out, int out_size)
{
    (void)in_sizes; (void)n_in; (void)out_size;
    const float* Qp = (const float*)d_in[0];
    const float* Kp = (const float*)d_in[1];
    const float* Vp = (const float*)d_in[2];
    const float* Mp = (const float*)d_in[3];
    float* Op = (float*)d_out;

    dim3 cgrid(NT, Hn, 3);
    convert_kernel<<<cgrid, 128>>>(Qp, Kp, Vp);

    cudaFuncSetAttribute(sdpa_hmma_kernel,
                         cudaFuncAttributeMaxDynamicSharedMemorySize, SMEM_TOTAL);
    dim3 grid(Hn, Sn / BQ);
    sdpa_hmma_kernel<<<grid, 128, SMEM_TOTAL>>>(Mp, Op);
}

// round 16
// speedup vs baseline: 9.1272x; 1.3179x over previous
#include <cuda_runtime.h>
#include <cuda_fp16.h>
#include <stdint.h>

// ============================================================================
// FA2-style flash attention, fp16 inputs / fp32 accumulation, via
// ldmatrix + mma.sync.m16n8k16 (base sm_103 target: tcgen05 unavailable).
//
// Kernels:
//  0) zero_flag / scan_mask: set g_mask_on = (mask has any nonzero), each run.
//  1) convert_kernel: Q/K/V fp32 -> fp16 pre-swizzled 8KB tile images
//     (Q pre-scaled by 0.125*log2(e)).
//  2) sdpa_hmma_kernel: 3-stage cp.async pipeline, log2-domain softmax,
//     uniform-branch mask application (skipped when mask is all zeros).
// ============================================================================

static constexpr int Hn = 16, Sn = 4096, Dn = 64;
static constexpr int BQ = 64, BK = 64;
static constexpr int NT = Sn / BK;           // 64 key tiles
static constexpr int TILE_ELEMS = 64 * 64;   // 4096 fp16 = 8KB

__device__ __half QT_g[Hn * NT * TILE_ELEMS];
__device__ __half KT_g[Hn * NT * TILE_ELEMS];
__device__ __half VT_g[Hn * NT * TILE_ELEMS];
__device__ int    g_mask_on;

// dynamic smem layout: Q staging doubles as V slot 2 after prologue
static constexpr int Q_OFF = 0;                    // 8KB (later: V slot 2)
static constexpr int K_OFF = 8192;                 // 3 x 8KB K slots
static constexpr int V_OFF = K_OFF + 3 * 8192;     // 2 x 8KB V slots (0,1)
static constexpr int SMEM_TOTAL = V_OFF + 2 * 8192;  // 49152 B

__device__ __forceinline__ uint32_t smem_u32(const void* p) {
    uint32_t a;
    asm("{ .reg .u64 t; cvta.to.shared.u64 t, %1; cvt.u32.u64 %0, t; }" : "=r"(a) : "l"(p));
    return a;
}
__device__ __forceinline__ float ex2f(float x) {
    float r;
    asm("ex2.approx.ftz.f32 %0, %1;" : "=f"(r) : "f"(x));
    return r;
}
__device__ __forceinline__ void ldsm4(uint32_t r[4], uint32_t addr) {
    asm volatile("ldmatrix.sync.aligned.m8n8.x4.shared.b16 {%0,%1,%2,%3}, [%4];"
                 : "=r"(r[0]), "=r"(r[1]), "=r"(r[2]), "=r"(r[3]) : "r"(addr));
}
__device__ __forceinline__ void ldsm4t(uint32_t r[4], uint32_t addr) {
    asm volatile("ldmatrix.sync.aligned.m8n8.x4.trans.shared.b16 {%0,%1,%2,%3}, [%4];"
                 : "=r"(r[0]), "=r"(r[1]), "=r"(r[2]), "=r"(r[3]) : "r"(addr));
}
__device__ __forceinline__ void mma16816(float c[4], const uint32_t a[4],
                                         uint32_t b0, uint32_t b1) {
    asm volatile(
        "mma.sync.aligned.m16n8k16.row.col.f32.f16.f16.f32 "
        "{%0,%1,%2,%3}, {%4,%5,%6,%7}, {%8,%9}, {%0,%1,%2,%3};"
        : "+f"(c[0]), "+f"(c[1]), "+f"(c[2]), "+f"(c[3])
        : "r"(a[0]), "r"(a[1]), "r"(a[2]), "r"(a[3]), "r"(b0), "r"(b1));
}
__device__ __forceinline__ void cpa16(uint32_t sdst, const void* gsrc) {
    asm volatile("cp.async.cg.shared.global [%0], [%1], 16;" :: "r"(sdst), "l"(gsrc));
}
#define CP_COMMIT() asm volatile("cp.async.commit_group;" ::: "memory")
#define CP_WAIT(n)  asm volatile("cp.async.wait_group %0;" :: "n"(n) : "memory")

// one 8KB tile: 128 threads x 4 x 16B
__device__ __forceinline__ void cpa_tile(uint32_t sdst, const char* gsrc, int tid) {
    #pragma unroll
    for (int it = 0; it < 4; ++it)
        cpa16(sdst + tid * 16 + it * 2048, gsrc + tid * 16 + it * 2048);
}

// ---------------------------------------------------------------------------
__global__ void zero_flag_kernel() { g_mask_on = 0; }

__global__ void __launch_bounds__(256)
scan_mask_kernel(const float4* __restrict__ M4, int n4) {
    bool nz = false;
    for (int i = blockIdx.x * blockDim.x + threadIdx.x; i < n4;
         i += gridDim.x * blockDim.x) {
        const float4 v = M4[i];
        nz |= (v.x != 0.0f) | (v.y != 0.0f) | (v.z != 0.0f) | (v.w != 0.0f);
    }
    if (__ballot_sync(0xffffffffu, nz)) {
        if ((threadIdx.x & 31) == 0) atomicOr(&g_mask_on, 1);
    }
}

// ---------------------------------------------------------------------------
// convert kernel: fp32 [64 x 64] block -> fp16 swizzled 8KB tile image.
// grid = (NT, Hn, 3). which: 0=Q (scaled), 1=K, 2=V.
// ---------------------------------------------------------------------------
__global__ void __launch_bounds__(128)
convert_kernel(const float* __restrict__ Q,
               const float* __restrict__ K,
               const float* __restrict__ V)
{
    constexpr float LOG2E = 1.4426950408889634f;
    const int tile = blockIdx.x, h = blockIdx.y, which = blockIdx.z;
    const int tid = threadIdx.x;

    const float* src = (which == 0 ? Q : which == 1 ? K : V)
                     + ((size_t)h * Sn + (size_t)tile * 64) * Dn;
    __half* dsth = (which == 0 ? QT_g : which == 1 ? KT_g : VT_g)
                 + (size_t)(h * NT + tile) * TILE_ELEMS;
    char* dst = reinterpret_cast<char*>(dsth);
    const float scale = (which == 0) ? 0.125f * LOG2E : 1.0f;

    #pragma unroll
    for (int it = 0; it < 8; ++it) {
        const int i = tid + it * 128;
        const int row = i >> 4, g = i & 15;
        float4 f = *reinterpret_cast<const float4*>(src + row * Dn + g * 4);
        __half2 h0 = __floats2half2_rn(f.x * scale, f.y * scale);
        __half2 h1 = __floats2half2_rn(f.z * scale, f.w * scale);
        const uint32_t byte = row * 128 + ((((g >> 1) ^ (row & 7)) << 4) | ((g & 1) << 3));
        *reinterpret_cast<__half2*>(dst + byte)     = h0;
        *reinterpret_cast<__half2*>(dst + byte + 4) = h1;
    }
}

// ---------------------------------------------------------------------------
// main attention kernel
// ---------------------------------------------------------------------------
__global__ void __launch_bounds__(128, 4)
sdpa_hmma_kernel(const float* __restrict__ M, float* __restrict__ O)
{
    extern __shared__ char smem[];
    const uint32_t sb = smem_u32(smem);

    const int tid = threadIdx.x;
    const int wid = tid >> 5;
    const int lid = tid & 31;
    const int g   = lid >> 2;
    const int t   = lid & 3;

    const int h   = blockIdx.x;   // heads adjacent: mask rows shared in L2
    const int qt  = blockIdx.y;
    const int q0  = qt * BQ;
    const int wq0 = wid * 16;

    constexpr float LOG2E = 1.4426950408889634f;
    const int mask_on = g_mask_on;   // uniform across grid

    const char* Qg = reinterpret_cast<const char*>(QT_g + (size_t)(h * NT + qt) * TILE_ELEMS);
    const char* Kg = reinterpret_cast<const char*>(KT_g + (size_t)h * NT * TILE_ELEMS);
    const char* Vg = reinterpret_cast<const char*>(VT_g + (size_t)h * NT * TILE_ELEMS);

    // ---- prologue: group0 = {Q, K0, V0}, group1 = {K1, V1} ----
    cpa_tile(sb + Q_OFF, Qg, tid);
    cpa_tile(sb + K_OFF, Kg, tid);
    cpa_tile(sb + V_OFF, Vg, tid);
    CP_COMMIT();
    cpa_tile(sb + K_OFF + 8192, Kg + 8192, tid);
    cpa_tile(sb + V_OFF + 8192, Vg + 8192, tid);
    CP_COMMIT();
    CP_WAIT(1);            // Q, K0, V0 landed
    __syncthreads();

    // ---- preload Q A-fragments (then Q region becomes V slot 2) ----
    uint32_t qa[4][4];
    {
        const int sel = lid >> 3;
        const int row = wq0 + (lid & 7) + ((sel & 1) << 3);
        #pragma unroll
        for (int ks = 0; ks < 4; ++ks) {
            const int chunk = 2 * ks + (sel >> 1);
            ldsm4(qa[ks], sb + Q_OFF + row * 128 + ((chunk ^ (row & 7)) << 4));
        }
    }
    __syncthreads();       // all warps read Q before V2 prefetch overwrites it

    float m0 = -1e30f, m1 = -1e30f, l0 = 0.0f, l1 = 0.0f;
    float oa[8][4];
    #pragma unroll
    for (int j = 0; j < 8; ++j)
        #pragma unroll
        for (int k = 0; k < 4; ++k) oa[j][k] = 0.0f;

    const float* mrow0 = M + (size_t)(q0 + wq0 + g) * Sn + 2 * t;
    const float* mrow1 = M + (size_t)(q0 + wq0 + g + 8) * Sn + 2 * t;

    for (int kt = 0; kt < NT; ++kt) {
        const int slot = kt % 3;
        const uint32_t kbase = sb + K_OFF + slot * 8192;
        const uint32_t vbase = sb + ((slot == 2) ? Q_OFF : V_OFF + slot * 8192);

        // ---- prefetch tile kt+2 into slot (kt+2)%3 ----
        const bool issued = (kt + 2 < NT);
        if (issued) {
            const int ps = (kt + 2) % 3;
            cpa_tile(sb + K_OFF + ps * 8192, Kg + (size_t)(kt + 2) * 8192, tid);
            cpa_tile(sb + ((ps == 2) ? Q_OFF : V_OFF + ps * 8192),
                     Vg + (size_t)(kt + 2) * 8192, tid);
            CP_COMMIT();
        }

        // ---- S(log2) = Q K^T ----
        float sc[8][4];
        #pragma unroll
        for (int j = 0; j < 8; ++j)
            #pragma unroll
            for (int k = 0; k < 4; ++k) sc[j][k] = 0.0f;

        {
            const int sel = lid >> 3;
            const int rlo = (lid & 7) + ((sel >> 1) << 3);
            #pragma unroll
            for (int ks = 0; ks < 4; ++ks) {
                const int chunk = 2 * ks + (sel & 1);
                #pragma unroll
                for (int j = 0; j < 4; ++j) {
                    const int row = 16 * j + rlo;
                    uint32_t kb[4];
                    ldsm4(kb, kbase + row * 128 + ((chunk ^ (row & 7)) << 4));
                    mma16816(sc[2 * j],     qa[ks], kb[0], kb[1]);
                    mma16816(sc[2 * j + 1], qa[ks], kb[2], kb[3]);
                }
            }
        }

        // ---- mask (only when mask has nonzero content; uniform branch) ----
        if (mask_on) {
            const float* mp0 = mrow0 + kt * BK;
            const float* mp1 = mrow1 + kt * BK;
            #pragma unroll
            for (int j = 0; j < 8; ++j) {
                const float2 v0 = __ldg(reinterpret_cast<const float2*>(mp0 + 8 * j));
                const float2 v1 = __ldg(reinterpret_cast<const float2*>(mp1 + 8 * j));
                sc[j][0] = fmaf(v0.x, LOG2E, sc[j][0]);
                sc[j][1] = fmaf(v0.y, LOG2E, sc[j][1]);
                sc[j][2] = fmaf(v1.x, LOG2E, sc[j][2]);
                sc[j][3] = fmaf(v1.y, LOG2E, sc[j][3]);
            }
        }

        // ---- online softmax (max over quad; l stays lane-partial) ----
        float rmax0 = sc[0][0], rmax1 = sc[0][2];
        #pragma unroll
        for (int j = 0; j < 8; ++j) {
            rmax0 = fmaxf(rmax0, fmaxf(sc[j][0], sc[j][1]));
            rmax1 = fmaxf(rmax1, fmaxf(sc[j][2], sc[j][3]));
        }
        #pragma unroll
        for (int sh = 1; sh < 4; sh <<= 1) {
            rmax0 = fmaxf(rmax0, __shfl_xor_sync(0xffffffffu, rmax0, sh));
            rmax1 = fmaxf(rmax1, __shfl_xor_sync(0xffffffffu, rmax1, sh));
        }
        const float mn0 = fmaxf(m0, rmax0), mn1 = fmaxf(m1, rmax1);
        const float a0 = ex2f(m0 - mn0), a1 = ex2f(m1 - mn1);
        m0 = mn0; m1 = mn1;

        float ps0 = 0.0f, ps1 = 0.0f;
        #pragma unroll
        for (int j = 0; j < 8; ++j) {
            sc[j][0] = ex2f(sc[j][0] - mn0); ps0 += sc[j][0];
            sc[j][1] = ex2f(sc[j][1] - mn0); ps0 += sc[j][1];
            sc[j][2] = ex2f(sc[j][2] - mn1); ps1 += sc[j][2];
            sc[j][3] = ex2f(sc[j][3] - mn1); ps1 += sc[j][3];
        }
        l0 = l0 * a0 + ps0;
        l1 = l1 * a1 + ps1;
        #pragma unroll
        for (int j = 0; j < 8; ++j) {
            oa[j][0] *= a0; oa[j][1] *= a0;
            oa[j][2] *= a1; oa[j][3] *= a1;
        }

        // ---- O += P V ----
        {
            const int sel = lid >> 3;
            const int rlo = (lid & 7) + ((sel & 1) << 3);
            #pragma unroll
            for (int j2 = 0; j2 < 4; ++j2) {
                uint32_t pa[4];
                {
                    __half2 hh;
                    hh = __floats2half2_rn(sc[2 * j2][0],     sc[2 * j2][1]);
                    pa[0] = *reinterpret_cast<uint32_t*>(&hh);
                    hh = __floats2half2_rn(sc[2 * j2][2],     sc[2 * j2][3]);
                    pa[1] = *reinterpret_cast<uint32_t*>(&hh);
                    hh = __floats2half2_rn(sc[2 * j2 + 1][0], sc[2 * j2 + 1][1]);
                    pa[2] = *reinterpret_cast<uint32_t*>(&hh);
                    hh = __floats2half2_rn(sc[2 * j2 + 1][2], sc[2 * j2 + 1][3]);
                    pa[3] = *reinterpret_cast<uint32_t*>(&hh);
                }
                const int row = 16 * j2 + rlo;
                #pragma unroll
                for (int dp = 0; dp < 4; ++dp) {
                    const int chunk = 2 * dp + (sel >> 1);
                    uint32_t vb[4];
                    ldsm4t(vb, vbase + row * 128 + ((chunk ^ (row & 7)) << 4));
                    mma16816(oa[2 * dp],     pa, vb[0], vb[1]);
                    mma16816(oa[2 * dp + 1], pa, vb[2], vb[3]);
                }
            }
        }

        // ---- pipeline wait: tile kt+1 must be resident before next iter ----
        if (issued) { CP_WAIT(1); } else { CP_WAIT(0); }
        __syncthreads();
    }

    // ---- epilogue: reduce l over quad, normalize, store fp32 ----
    #pragma unroll
    for (int sh = 1; sh < 4; sh <<= 1) {
        l0 += __shfl_xor_sync(0xffffffffu, l0, sh);
        l1 += __shfl_xor_sync(0xffffffffu, l1, sh);
    }
    const float i0 = 1.0f / l0, i1 = 1.0f / l1;
    float* or0 = O + (size_t)(h * Sn + q0 + wq0 + g) * Dn + 2 * t;
    float* or1 = or0 + 8 * Dn;
    #pragma unroll
    for (int j = 0; j < 8; ++j) {
        float2 v0 = make_float2(oa[j][0] * i0, oa[j][1] * i0);
        float2 v1 = make_float2(oa[j][2] * i1, oa[j][3] * i1);
        *reinterpret_cast<float2*>(or0 + 8 * j) = v0;
        *reinterpret_cast<float2*>(or1 + 8 * j) = v1;
    }
}

extern "C" void kernel_launch(void* const* d_in, const int* in_sizes, int n_in,
                              void* d_out, int out_size)
{
    (void)in_sizes; (void)n_in; (void)out_size;
    const float* Qp = (const float*)d_in[0];
    const float* Kp = (const float*)d_in[1];
    const float* Vp = (const float*)d_in[2];
    const float* Mp = (const float*)d_in[3];
    float* Op = (float*)d_out;

    zero_flag_kernel<<<1, 1>>>();
    scan_mask_kernel<<<2048, 256>>>(reinterpret_cast<const float4*>(Mp),
                                    Sn * Sn / 4);
    dim3 cgrid(NT, Hn, 3);
    convert_kernel<<<cgrid, 128>>>(Qp, Kp, Vp);

    cudaFuncSetAttribute(sdpa_hmma_kernel,
                         cudaFuncAttributeMaxDynamicSharedMemorySize, SMEM_TOTAL);
    dim3 grid(Hn, Sn / BQ);
    sdpa_hmma_kernel<<<grid, 128, SMEM_TOTAL>>>(Mp, Op);
}